// round 2
// baseline (speedup 1.0000x reference)
#include <cuda_runtime.h>

#define B_  4096
#define T_  256
#define D_  20
#define E_  64
#define H_  16
#define G4_ 64
#define XPAD 21

__device__ float g_G[(size_t)B_ * G4_ * T_];   // [b][gate_col][t]
__device__ float g_hf[B_ * H_];
__device__ float g_hb[B_ * H_];

typedef unsigned long long u64;

__device__ __forceinline__ float ex2a(float x){ float y; asm("ex2.approx.f32 %0,%1;":"=f"(y):"f"(x)); return y; }
__device__ __forceinline__ float rcpa(float x){ float y; asm("rcp.approx.f32 %0,%1;":"=f"(y):"f"(x)); return y; }
__device__ __forceinline__ u64 pack2(float a,float b){ u64 r; asm("mov.b64 %0,{%1,%2};":"=l"(r):"f"(a),"f"(b)); return r; }
__device__ __forceinline__ void unpack2(u64 v,float&a,float&b){ asm("mov.b64 {%0,%1},%2;":"=f"(a),"=f"(b):"l"(v)); }
__device__ __forceinline__ u64 fma2(u64 a,u64 b,u64 c){ u64 d; asm("fma.rn.f32x2 %0,%1,%2,%3;":"=l"(d):"l"(a),"l"(b),"l"(c)); return d; }

// ---------------- Phase 1: per batch row, G[b,c,t] ----------------
__global__ void __launch_bounds__(256) k_phase1(
    const float* __restrict__ x, const float* __restrict__ W0,
    const float* __restrict__ b0, const float* __restrict__ Wf,
    const float* __restrict__ bf)
{
    extern __shared__ float sm[];
    float* Xs  = sm;                 // [256][XPAD]
    float* W0s = Xs + T_ * XPAD;     // [20][64]
    float* b0s = W0s + D_ * E_;      // [64]
    float* Ws  = b0s + 64;           // [64][64]
    float* bfs = Ws + E_ * G4_;      // [64]
    float* HEt = bfs + 64;           // [64][256] k-major

    const int tid = threadIdx.x;
    const int b   = blockIdx.x;
    const float* xb = x + (size_t)b * T_ * D_;

    for (int i = tid; i < T_ * D_; i += 256) { int r = i / D_, d = i - r * D_; Xs[r * XPAD + d] = xb[i]; }
    for (int i = tid; i < D_ * E_;  i += 256) W0s[i] = W0[i];
    for (int i = tid; i < E_ * G4_; i += 256) Ws[i]  = Wf[i];
    if (tid < 64) { b0s[tid] = b0[tid]; bfs[tid] = bf[tid]; }
    __syncthreads();

    { // Step A: HEt[k][t] = relu(x@W0+b0)
        const int rg = tid & 63;
        const int kb = (tid >> 6) * 16;
        u64 accp[8][4];
        #pragma unroll
        for (int j = 0; j < 8; j++) {
            u64 bj = pack2(b0s[kb + 2*j], b0s[kb + 2*j + 1]);
            #pragma unroll
            for (int i = 0; i < 4; i++) accp[j][i] = bj;
        }
        #pragma unroll 4
        for (int d = 0; d < D_; d++) {
            u64 xp[4];
            #pragma unroll
            for (int i = 0; i < 4; i++) { float xv = Xs[(rg + 64*i) * XPAD + d]; xp[i] = pack2(xv, xv); }
            const u64* wrow = (const u64*)&W0s[d * E_ + kb];
            #pragma unroll
            for (int j = 0; j < 8; j++) {
                u64 wj = wrow[j];
                #pragma unroll
                for (int i = 0; i < 4; i++) accp[j][i] = fma2(xp[i], wj, accp[j][i]);
            }
        }
        #pragma unroll
        for (int j = 0; j < 8; j++)
            #pragma unroll
            for (int i = 0; i < 4; i++) {
                float v0, v1; unpack2(accp[j][i], v0, v1);
                HEt[(kb + 2*j)     * T_ + rg + 64*i] = fmaxf(v0, 0.f);
                HEt[(kb + 2*j + 1) * T_ + rg + 64*i] = fmaxf(v1, 0.f);
            }
    }
    __syncthreads();

    { // Step B: G[b,c,t] = bf[c] + sum_k HEt[k][t]*Ws[k][c]
        const int c0 = (tid & 7) * 8, t0 = (tid >> 3) * 8;
        u64 accp[8][4];
        #pragma unroll
        for (int i = 0; i < 8; i++)
            #pragma unroll
            for (int j = 0; j < 4; j++) accp[i][j] = 0ULL;
        #pragma unroll 4
        for (int k = 0; k < E_; k++) {
            const float4* ha = (const float4*)&HEt[k * T_ + t0];
            float4 a0 = ha[0], a1 = ha[1];
            const ulonglong2* wb = (const ulonglong2*)&Ws[k * G4_ + c0];
            ulonglong2 w01 = wb[0], w23 = wb[1];
            float av[8] = {a0.x,a0.y,a0.z,a0.w,a1.x,a1.y,a1.z,a1.w};
            #pragma unroll
            for (int i = 0; i < 8; i++) {
                u64 ap = pack2(av[i], av[i]);
                accp[i][0] = fma2(ap, w01.x, accp[i][0]);
                accp[i][1] = fma2(ap, w01.y, accp[i][1]);
                accp[i][2] = fma2(ap, w23.x, accp[i][2]);
                accp[i][3] = fma2(ap, w23.y, accp[i][3]);
            }
        }
        float* Gb = g_G + (size_t)b * G4_ * T_;
        #pragma unroll
        for (int j = 0; j < 4; j++) {
            float bL = bfs[c0 + 2*j], bR = bfs[c0 + 2*j + 1];
            float vL[8], vR[8];
            #pragma unroll
            for (int i = 0; i < 8; i++) { unpack2(accp[i][j], vL[i], vR[i]); vL[i] += bL; vR[i] += bR; }
            float4* pL = (float4*)&Gb[(c0 + 2*j)     * T_ + t0];
            float4* pR = (float4*)&Gb[(c0 + 2*j + 1) * T_ + t0];
            pL[0] = make_float4(vL[0],vL[1],vL[2],vL[3]);
            pL[1] = make_float4(vL[4],vL[5],vL[6],vL[7]);
            pR[0] = make_float4(vR[0],vR[1],vR[2],vR[3]);
            pR[1] = make_float4(vR[4],vR[5],vR[6],vR[7]);
        }
    }
}

// ---------------- Phase 2: forward scan, warp per row ----------------
__global__ void __launch_bounds__(256) k_scan(const float* __restrict__ Wf)
{
    __shared__ __align__(16) float2 hsh[8][16];
    const int tid = threadIdx.x, w = tid >> 5, l = tid & 31;
    const int b = blockIdx.x * 8 + w;
    const int j = l & 15;
    const int cA = (l < 16) ? l : (32 + j);
    const int cB = cA + 16;

    u64 wp[16];
    #pragma unroll
    for (int k = 0; k < 16; k++)
        wp[k] = pack2(Wf[(E_ + k) * G4_ + cA], Wf[(E_ + k) * G4_ + cB]);

    const float4* pA = (const float4*)(g_G + ((size_t)b * G4_ + cA) * T_);
    const float4* pB = (const float4*)(g_G + ((size_t)b * G4_ + cB) * T_);

    float h = 0.f, c = 0.f;
    if (l < 16) hsh[w][l] = make_float2(0.f, 0.f);
    __syncwarp();

    const float L2E = 1.4426950408889634f;
    float kU, bU, kV, aV, bV;
    if (l < 16) { kU = -L2E; bU = 0.f;   kV = -2.f * L2E; aV = 2.f; bV = -1.f; }
    else        { kU = -L2E; bU = -L2E;  kV = -L2E;       aV = 1.f; bV =  0.f; }

    float4 cA0 = pA[0], cA1 = pA[1], cB0 = pB[0], cB1 = pB[1];
    float4 nA0, nA1, nB0, nB1;

    for (int tg = 0; tg < T_ / 8; ++tg) {
        if (tg < T_ / 8 - 1) {
            nA0 = pA[tg*2 + 2]; nA1 = pA[tg*2 + 3];
            nB0 = pB[tg*2 + 2]; nB1 = pB[tg*2 + 3];
        }
        float ga[8] = {cA0.x,cA0.y,cA0.z,cA0.w,cA1.x,cA1.y,cA1.z,cA1.w};
        float gb[8] = {cB0.x,cB0.y,cB0.z,cB0.w,cB1.x,cB1.y,cB1.z,cB1.w};
        #pragma unroll
        for (int i = 0; i < 8; i++) {
            const ulonglong2* hp = (const ulonglong2*)&hsh[w][0];
            ulonglong2 h01 = hp[0], h23 = hp[1], h45 = hp[2], h67 = hp[3];
            ulonglong2 h89 = hp[4], hab = hp[5], hcd = hp[6], hef = hp[7];
            u64 acc = pack2(ga[i], gb[i]);
            acc = fma2(h01.x, wp[0],  acc); acc = fma2(h01.y, wp[1],  acc);
            acc = fma2(h23.x, wp[2],  acc); acc = fma2(h23.y, wp[3],  acc);
            acc = fma2(h45.x, wp[4],  acc); acc = fma2(h45.y, wp[5],  acc);
            acc = fma2(h67.x, wp[6],  acc); acc = fma2(h67.y, wp[7],  acc);
            acc = fma2(h89.x, wp[8],  acc); acc = fma2(h89.y, wp[9],  acc);
            acc = fma2(hab.x, wp[10], acc); acc = fma2(hab.y, wp[11], acc);
            acc = fma2(hcd.x, wp[12], acc); acc = fma2(hcd.y, wp[13], acc);
            acc = fma2(hef.x, wp[14], acc); acc = fma2(hef.y, wp[15], acc);
            float xA, xB; unpack2(acc, xA, xB);

            float u = rcpa(1.f + ex2a(fmaf(kU, xA, bU)));
            float v = fmaf(aV, rcpa(1.f + ex2a(kV * xB)), bV);
            float sf = __shfl_down_sync(0xffffffffu, u, 16);
            float so = __shfl_down_sync(0xffffffffu, v, 16);
            if (l < 16) {
                c = fmaf(sf, c, u * v);
                float th = fmaf(2.f, rcpa(1.f + ex2a(-2.f * L2E * c)), -1.f);
                h = so * th;
                hsh[w][l] = make_float2(h, h);
            }
            __syncwarp();
        }
        cA0 = nA0; cA1 = nA1; cB0 = nB0; cB1 = nB1;
    }
    if (l < 16) g_hf[b * H_ + l] = h;
}

// ---------------- Backward LSTM: single step at t=T-1 ----------------
__global__ void __launch_bounds__(256) k_bwdlast(
    const float* __restrict__ x, const float* __restrict__ W0,
    const float* __restrict__ b0, const float* __restrict__ Wb,
    const float* __restrict__ bb)
{
    __shared__ float W0s[D_ * E_];
    __shared__ float Wbs[E_ * G4_];
    __shared__ float b0s[64], bbs[64];
    __shared__ float xsh[8][20];
    __shared__ __align__(16) float2 hes[8][64];

    const int tid = threadIdx.x, w = tid >> 5, l = tid & 31;
    const int b = blockIdx.x * 8 + w;

    for (int i = tid; i < D_ * E_;  i += 256) W0s[i] = W0[i];
    for (int i = tid; i < E_ * G4_; i += 256) Wbs[i] = Wb[i];
    if (tid < 64) { b0s[tid] = b0[tid]; bbs[tid] = bb[tid]; }
    __syncthreads();

    if (l < 20) xsh[w][l] = x[((size_t)b * T_ + (T_ - 1)) * D_ + l];
    __syncwarp();

    float a0 = b0s[l], a1 = b0s[l + 32];
    #pragma unroll
    for (int d = 0; d < D_; d++) {
        float xv = xsh[w][d];
        a0 = fmaf(xv, W0s[d * E_ + l],      a0);
        a1 = fmaf(xv, W0s[d * E_ + l + 32], a1);
    }
    a0 = fmaxf(a0, 0.f); a1 = fmaxf(a1, 0.f);
    hes[w][l]      = make_float2(a0, a0);
    hes[w][l + 32] = make_float2(a1, a1);
    __syncwarp();

    const int j = l & 15;
    const int cA = (l < 16) ? l : (32 + j);
    const int cB = cA + 16;
    u64 acc = pack2(bbs[cA], bbs[cB]);
    #pragma unroll 8
    for (int k = 0; k < E_; k++) {
        u64 hd = *(const u64*)&hes[w][k];
        acc = fma2(hd, pack2(Wbs[k * G4_ + cA], Wbs[k * G4_ + cB]), acc);
    }
    float xA, xB; unpack2(acc, xA, xB);

    const float L2E = 1.4426950408889634f;
    float kU, bU, kV, aV, bV;
    if (l < 16) { kU = -L2E; bU = 0.f;  kV = -2.f * L2E; aV = 2.f; bV = -1.f; }
    else        { kU = -L2E; bU = -L2E; kV = -L2E;       aV = 1.f; bV =  0.f; }
    float u = rcpa(1.f + ex2a(fmaf(kU, xA, bU)));
    float v = fmaf(aV, rcpa(1.f + ex2a(kV * xB)), bV);
    float so = __shfl_down_sync(0xffffffffu, v, 16);
    if (l < 16) {
        float cc = u * v;
        float th = fmaf(2.f, rcpa(1.f + ex2a(-2.f * L2E * cc)), -1.f);
        g_hb[b * H_ + l] = so * th;
    }
}

// ---------------- Head MLP ----------------
__global__ void __launch_bounds__(256) k_head(
    const float* __restrict__ W1, const float* __restrict__ b1,
    const float* __restrict__ W2, const float* __restrict__ b2,
    const float* __restrict__ W3, const float* __restrict__ b3,
    float* __restrict__ out)
{
    __shared__ float W1s[32 * 64], W2s[64 * 16], W3s[32];
    __shared__ float b1s[64], b2s[16], b3s[2];
    __shared__ float insh[8][32], ush[8][64], vsh[8][16];

    const int tid = threadIdx.x, w = tid >> 5, l = tid & 31;
    const int b = blockIdx.x * 8 + w;

    for (int i = tid; i < 32 * 64; i += 256) W1s[i] = W1[i];
    for (int i = tid; i < 64 * 16; i += 256) W2s[i] = W2[i];
    if (tid < 32) W3s[tid] = W3[tid];
    if (tid < 64) b1s[tid] = b1[tid];
    if (tid < 16) b2s[tid] = b2[tid];
    if (tid < 2)  b3s[tid] = b3[tid];
    __syncthreads();

    insh[w][l] = (l < 16) ? g_hf[b * H_ + l] : g_hb[b * H_ + (l - 16)];
    __syncwarp();

    float a0 = b1s[l], a1 = b1s[l + 32];
    #pragma unroll 8
    for (int k = 0; k < 32; k++) {
        float t = insh[w][k];
        a0 = fmaf(t, W1s[k * 64 + l],      a0);
        a1 = fmaf(t, W1s[k * 64 + l + 32], a1);
    }
    ush[w][l]      = fmaxf(a0, 0.f);
    ush[w][l + 32] = fmaxf(a1, 0.f);
    __syncwarp();

    if (l < 16) {
        float a = b2s[l];
        #pragma unroll 8
        for (int k = 0; k < 64; k++) a = fmaf(ush[w][k], W2s[k * 16 + l], a);
        vsh[w][l] = fmaxf(a, 0.f);
    }
    __syncwarp();

    if (l < 2) {
        float a = b3s[l];
        #pragma unroll
        for (int k = 0; k < 16; k++) a = fmaf(vsh[w][k], W3s[k * 2 + l], a);
        out[b * 2 + l] = a;
    }
}

extern "C" void kernel_launch(void* const* d_in, const int* in_sizes, int n_in,
                              void* d_out, int out_size)
{
    (void)in_sizes; (void)n_in; (void)out_size;
    const float* x  = (const float*)d_in[0];
    const float* W0 = (const float*)d_in[1];
    const float* b0 = (const float*)d_in[2];
    const float* Wf = (const float*)d_in[3];
    const float* bf = (const float*)d_in[4];
    const float* Wb = (const float*)d_in[5];
    const float* bb = (const float*)d_in[6];
    const float* W1 = (const float*)d_in[7];
    const float* b1 = (const float*)d_in[8];
    const float* W2 = (const float*)d_in[9];
    const float* b2 = (const float*)d_in[10];
    const float* W3 = (const float*)d_in[11];
    const float* b3 = (const float*)d_in[12];
    float* out = (float*)d_out;

    const int smem1 = (T_ * XPAD + D_ * E_ + 64 + E_ * G4_ + 64 + E_ * T_) * (int)sizeof(float);
    cudaFuncSetAttribute(k_phase1, cudaFuncAttributeMaxDynamicSharedMemorySize, smem1);

    k_phase1 <<<B_,     256, smem1>>>(x, W0, b0, Wf, bf);
    k_bwdlast<<<B_ / 8, 256>>>(x, W0, b0, Wb, bb);
    k_scan   <<<B_ / 8, 256>>>(Wf);
    k_head   <<<B_ / 8, 256>>>(W1, b1, W2, b2, W3, b3, out);
}

// round 3
// speedup vs baseline: 1.0862x; 1.0862x over previous
#include <cuda_runtime.h>

#define B_  4096
#define T_  256
#define D_  20
#define E_  64
#define H_  16
#define G4_ 64
#define XPAD 21
#define TGRP 32          // 256/8 time-groups
#define SGROW 80         // swizzled smem row stride (floats)

// G layout: [b][tg(32)][ti(8)][c(64)]  (2KB contiguous per (b,tg))
__device__ float g_G[(size_t)B_ * G4_ * T_];
__device__ float g_hf[B_ * H_];

typedef unsigned long long u64;

__device__ __forceinline__ float ex2a(float x){ float y; asm("ex2.approx.f32 %0,%1;":"=f"(y):"f"(x)); return y; }
__device__ __forceinline__ float rcpa(float x){ float y; asm("rcp.approx.f32 %0,%1;":"=f"(y):"f"(x)); return y; }
__device__ __forceinline__ u64 pack2(float a,float b){ u64 r; asm("mov.b64 %0,{%1,%2};":"=l"(r):"f"(a),"f"(b)); return r; }
__device__ __forceinline__ void unpack2(u64 v,float&a,float&b){ asm("mov.b64 {%0,%1},%2;":"=f"(a),"=f"(b):"l"(v)); }
__device__ __forceinline__ u64 fma2(u64 a,u64 b,u64 c){ u64 d; asm("fma.rn.f32x2 %0,%1,%2,%3;":"=l"(d):"l"(a),"l"(b),"l"(c)); return d; }
__device__ __forceinline__ u64 add2(u64 a,u64 b){ u64 d; asm("add.rn.f32x2 %0,%1,%2;":"=l"(d):"l"(a),"l"(b)); return d; }

// ---------------- Phase 1 ----------------
__global__ void __launch_bounds__(256, 2) k_phase1(
    const float* __restrict__ x, const float* __restrict__ W0,
    const float* __restrict__ b0, const float* __restrict__ Wf,
    const float* __restrict__ bf)
{
    extern __shared__ float sm[];
    float* Xs  = sm;                 // [256][XPAD]
    float* W0s = Xs + T_ * XPAD;     // [20][64]
    float* b0s = W0s + D_ * E_;      // [64]
    float* Ws  = b0s + 64;           // [64][64]
    float* bfs = Ws + E_ * G4_;      // [64]
    float* HEt = bfs + 64;           // [64][256] k-major

    const int tid = threadIdx.x;
    const int b   = blockIdx.x;
    const float* xb = x + (size_t)b * T_ * D_;

    for (int i = tid; i < T_ * D_; i += 256) { int r = i / D_, d = i - r * D_; Xs[r * XPAD + d] = xb[i]; }
    for (int i = tid; i < D_ * E_;  i += 256) W0s[i] = W0[i];
    for (int i = tid; i < E_ * G4_; i += 256) Ws[i]  = Wf[i];
    if (tid < 64) { b0s[tid] = b0[tid]; bfs[tid] = bf[tid]; }
    __syncthreads();

    { // Step A: HEt[k][t] = relu(x@W0+b0)
        const int rg = tid & 63;
        const int kb = (tid >> 6) * 16;
        u64 accp[8][4];
        #pragma unroll
        for (int j = 0; j < 8; j++) {
            u64 bj = pack2(b0s[kb + 2*j], b0s[kb + 2*j + 1]);
            #pragma unroll
            for (int i = 0; i < 4; i++) accp[j][i] = bj;
        }
        #pragma unroll 4
        for (int d = 0; d < D_; d++) {
            u64 xp[4];
            #pragma unroll
            for (int i = 0; i < 4; i++) { float xv = Xs[(rg + 64*i) * XPAD + d]; xp[i] = pack2(xv, xv); }
            const u64* wrow = (const u64*)&W0s[d * E_ + kb];
            #pragma unroll
            for (int j = 0; j < 8; j++) {
                u64 wj = wrow[j];
                #pragma unroll
                for (int i = 0; i < 4; i++) accp[j][i] = fma2(xp[i], wj, accp[j][i]);
            }
        }
        #pragma unroll
        for (int j = 0; j < 8; j++)
            #pragma unroll
            for (int i = 0; i < 4; i++) {
                float v0, v1; unpack2(accp[j][i], v0, v1);
                HEt[(kb + 2*j)     * T_ + rg + 64*i] = fmaxf(v0, 0.f);
                HEt[(kb + 2*j + 1) * T_ + rg + 64*i] = fmaxf(v1, 0.f);
            }
    }
    __syncthreads();

    { // Step B -> G[b][tg][ti][c]
        const int c0 = (tid & 7) * 8;
        const int tg = tid >> 3;        // 0..31
        const int t0 = tg * 8;
        u64 accp[8][4];
        #pragma unroll
        for (int i = 0; i < 8; i++)
            #pragma unroll
            for (int j = 0; j < 4; j++) accp[i][j] = 0ULL;
        #pragma unroll 2
        for (int k = 0; k < E_; k++) {
            const float4* ha = (const float4*)&HEt[k * T_ + t0];
            float4 a0 = ha[0], a1 = ha[1];
            const ulonglong2* wb = (const ulonglong2*)&Ws[k * G4_ + c0];
            ulonglong2 w01 = wb[0], w23 = wb[1];
            float av[8] = {a0.x,a0.y,a0.z,a0.w,a1.x,a1.y,a1.z,a1.w};
            #pragma unroll
            for (int i = 0; i < 8; i++) {
                u64 ap = pack2(av[i], av[i]);
                accp[i][0] = fma2(ap, w01.x, accp[i][0]);
                accp[i][1] = fma2(ap, w01.y, accp[i][1]);
                accp[i][2] = fma2(ap, w23.x, accp[i][2]);
                accp[i][3] = fma2(ap, w23.y, accp[i][3]);
            }
        }
        float bia[8];
        #pragma unroll
        for (int j = 0; j < 8; j++) bia[j] = bfs[c0 + j];
        float* Gb = g_G + (size_t)b * (G4_ * T_) + tg * 512 + c0;
        #pragma unroll
        for (int i = 0; i < 8; i++) {
            float v0,v1,v2,v3,v4,v5,v6,v7;
            unpack2(accp[i][0], v0, v1);
            unpack2(accp[i][1], v2, v3);
            unpack2(accp[i][2], v4, v5);
            unpack2(accp[i][3], v6, v7);
            float4 fa = make_float4(v0+bia[0], v1+bia[1], v2+bia[2], v3+bia[3]);
            float4 fb = make_float4(v4+bia[4], v5+bia[5], v6+bia[6], v7+bia[7]);
            *(float4*)(Gb + i * 64)     = fa;
            *(float4*)(Gb + i * 64 + 4) = fb;
        }
    }
}

// ---------------- Phase 2: forward scan (4 warps/CTA) ----------------
__global__ void __launch_bounds__(128) k_scan(const float* __restrict__ Wf)
{
    __shared__ float sg[4][2][8 * SGROW];            // swizzled gate stage
    __shared__ __align__(16) float2 hsh[4][16];

    const int tid = threadIdx.x, w = tid >> 5, l = tid & 31;
    const int b = blockIdx.x * 4 + w;
    const int j = l & 15;
    const int cA = (l < 16) ? l : (32 + j);
    const int cB = cA + 16;
    const int offA = cA + ((cA >> 5) << 4);
    const int offB = cB + ((cB >> 5) << 4);

    u64 wp[16];
    #pragma unroll
    for (int k = 0; k < 16; k++)
        wp[k] = pack2(Wf[(E_ + k) * G4_ + cA], Wf[(E_ + k) * G4_ + cB]);

    const float* Gb = g_G + (size_t)b * (G4_ * T_);

    // per-lane smem store offsets for staged group (4 float4 per lane)
    int soff[4];
    #pragma unroll
    for (int k = 0; k < 4; k++) {
        int f  = l + 32 * k;            // float4 index 0..127
        int ti = f >> 4;
        int c4 = f & 15;
        soff[k] = ti * SGROW + c4 * 4 + ((c4 >> 3) << 4);
    }

    float h = 0.f, c = 0.f;
    if (l < 16) hsh[w][l] = make_float2(0.f, 0.f);

    const float L2E = 1.4426950408889634f;
    float kU, bU, kV, aV, bV;
    if (l < 16) { kU = -L2E; bU = 0.f;   kV = -2.f * L2E; aV = 2.f; bV = -1.f; }
    else        { kU = -L2E; bU = -L2E;  kV = -L2E;       aV = 1.f; bV =  0.f; }

    // preload group 0
    float4 r[4];
    {
        const float4* src = (const float4*)Gb;
        #pragma unroll
        for (int k = 0; k < 4; k++) r[k] = src[l + 32 * k];
        #pragma unroll
        for (int k = 0; k < 4; k++) *(float4*)&sg[w][0][soff[k]] = r[k];
    }
    __syncwarp();

    for (int tg = 0; tg < TGRP; ++tg) {
        const int buf = tg & 1;
        if (tg < TGRP - 1) {
            const float4* src = (const float4*)(Gb + (size_t)(tg + 1) * 512);
            #pragma unroll
            for (int k = 0; k < 4; k++) r[k] = src[l + 32 * k];
        }
        const float* sgb = &sg[w][buf][0];
        #pragma unroll
        for (int i = 0; i < 8; i++) {
            float ga = sgb[i * SGROW + offA];
            float gb = sgb[i * SGROW + offB];
            const ulonglong2* hp = (const ulonglong2*)&hsh[w][0];
            ulonglong2 h01 = hp[0], h23 = hp[1], h45 = hp[2], h67 = hp[3];
            ulonglong2 h89 = hp[4], hab = hp[5], hcd = hp[6], hef = hp[7];
            u64 a0p = pack2(ga, gb);
            a0p = fma2(h01.x, wp[0],  a0p); a0p = fma2(h01.y, wp[1],  a0p);
            a0p = fma2(h23.x, wp[2],  a0p); a0p = fma2(h23.y, wp[3],  a0p);
            u64 a1p = fma2(h45.x, wp[4], 0ULL); a1p = fma2(h45.y, wp[5],  a1p);
            a1p = fma2(h67.x, wp[6],  a1p); a1p = fma2(h67.y, wp[7],  a1p);
            u64 a2p = fma2(h89.x, wp[8], 0ULL); a2p = fma2(h89.y, wp[9],  a2p);
            a2p = fma2(hab.x, wp[10], a2p); a2p = fma2(hab.y, wp[11], a2p);
            u64 a3p = fma2(hcd.x, wp[12], 0ULL); a3p = fma2(hcd.y, wp[13], a3p);
            a3p = fma2(hef.x, wp[14], a3p); a3p = fma2(hef.y, wp[15], a3p);
            u64 acc = add2(add2(a0p, a1p), add2(a2p, a3p));
            float xA, xB; unpack2(acc, xA, xB);

            float u = rcpa(1.f + ex2a(fmaf(kU, xA, bU)));
            float v = fmaf(aV, rcpa(1.f + ex2a(kV * xB)), bV);
            float sf = __shfl_down_sync(0xffffffffu, u, 16);
            float so = __shfl_down_sync(0xffffffffu, v, 16);
            if (l < 16) {
                c = fmaf(sf, c, u * v);
                float th = fmaf(2.f, rcpa(1.f + ex2a(-2.f * L2E * c)), -1.f);
                h = so * th;
                hsh[w][l] = make_float2(h, h);
            }
            __syncwarp();
        }
        if (tg < TGRP - 1) {
            #pragma unroll
            for (int k = 0; k < 4; k++) *(float4*)&sg[w][buf ^ 1][soff[k]] = r[k];
            __syncwarp();
        }
    }
    if (l < 16) g_hf[b * H_ + l] = h;
}

// ---------------- Tail: bwd single step + head MLP ----------------
__global__ void __launch_bounds__(256) k_tail(
    const float* __restrict__ x, const float* __restrict__ W0,
    const float* __restrict__ b0, const float* __restrict__ Wb,
    const float* __restrict__ bb,
    const float* __restrict__ W1, const float* __restrict__ b1,
    const float* __restrict__ W2, const float* __restrict__ b2,
    const float* __restrict__ W3, const float* __restrict__ b3,
    float* __restrict__ out)
{
    __shared__ float W0s[D_ * E_];
    __shared__ float Wbs[E_ * G4_];
    __shared__ float b0s[64], bbs[64];
    __shared__ float W1s[32 * 64], W2s[64 * 16], W3s[32];
    __shared__ float b1s[64], b2s[16], b3s[2];
    __shared__ float xsh[8][20];
    __shared__ __align__(16) float2 hes[8][64];
    __shared__ float hbs[8][16];
    __shared__ float insh[8][32], ush[8][64], vsh[8][16];

    const int tid = threadIdx.x, w = tid >> 5, l = tid & 31;
    const int b = blockIdx.x * 8 + w;

    for (int i = tid; i < D_ * E_;  i += 256) W0s[i] = W0[i];
    for (int i = tid; i < E_ * G4_; i += 256) Wbs[i] = Wb[i];
    for (int i = tid; i < 32 * 64;  i += 256) W1s[i] = W1[i];
    for (int i = tid; i < 64 * 16;  i += 256) W2s[i] = W2[i];
    if (tid < 32) W3s[tid] = W3[tid];
    if (tid < 64) { b0s[tid] = b0[tid]; bbs[tid] = bb[tid]; b1s[tid] = b1[tid]; }
    if (tid < 16) b2s[tid] = b2[tid];
    if (tid < 2)  b3s[tid] = b3[tid];
    __syncthreads();

    if (l < 20) xsh[w][l] = x[((size_t)b * T_ + (T_ - 1)) * D_ + l];
    __syncwarp();

    // hE at t = T-1
    float a0 = b0s[l], a1 = b0s[l + 32];
    #pragma unroll
    for (int d = 0; d < D_; d++) {
        float xv = xsh[w][d];
        a0 = fmaf(xv, W0s[d * E_ + l],      a0);
        a1 = fmaf(xv, W0s[d * E_ + l + 32], a1);
    }
    a0 = fmaxf(a0, 0.f); a1 = fmaxf(a1, 0.f);
    hes[w][l]      = make_float2(a0, a0);
    hes[w][l + 32] = make_float2(a1, a1);
    __syncwarp();

    const int j = l & 15;
    const int cA = (l < 16) ? l : (32 + j);
    const int cB = cA + 16;
    u64 acc = pack2(bbs[cA], bbs[cB]);
    #pragma unroll 8
    for (int k = 0; k < E_; k++) {
        u64 hd = *(const u64*)&hes[w][k];
        acc = fma2(hd, pack2(Wbs[k * G4_ + cA], Wbs[k * G4_ + cB]), acc);
    }
    float xA, xB; unpack2(acc, xA, xB);

    const float L2E = 1.4426950408889634f;
    float kU, bU, kV, aV, bV;
    if (l < 16) { kU = -L2E; bU = 0.f;  kV = -2.f * L2E; aV = 2.f; bV = -1.f; }
    else        { kU = -L2E; bU = -L2E; kV = -L2E;       aV = 1.f; bV =  0.f; }
    float u = rcpa(1.f + ex2a(fmaf(kU, xA, bU)));
    float v = fmaf(aV, rcpa(1.f + ex2a(kV * xB)), bV);
    float so = __shfl_down_sync(0xffffffffu, v, 16);
    if (l < 16) {
        float cc = u * v;
        float th = fmaf(2.f, rcpa(1.f + ex2a(-2.f * L2E * cc)), -1.f);
        hbs[w][l] = so * th;
    }
    __syncwarp();

    // head MLP
    insh[w][l] = (l < 16) ? g_hf[b * H_ + l] : hbs[w][l - 16];
    __syncwarp();

    float u0 = b1s[l], u1 = b1s[l + 32];
    #pragma unroll 8
    for (int k = 0; k < 32; k++) {
        float t = insh[w][k];
        u0 = fmaf(t, W1s[k * 64 + l],      u0);
        u1 = fmaf(t, W1s[k * 64 + l + 32], u1);
    }
    ush[w][l]      = fmaxf(u0, 0.f);
    ush[w][l + 32] = fmaxf(u1, 0.f);
    __syncwarp();

    if (l < 16) {
        float a = b2s[l];
        #pragma unroll 8
        for (int k = 0; k < 64; k++) a = fmaf(ush[w][k], W2s[k * 16 + l], a);
        vsh[w][l] = fmaxf(a, 0.f);
    }
    __syncwarp();

    if (l < 2) {
        float a = b3s[l];
        #pragma unroll
        for (int k = 0; k < 16; k++) a = fmaf(vsh[w][k], W3s[k * 2 + l], a);
        out[b * 2 + l] = a;
    }
}

extern "C" void kernel_launch(void* const* d_in, const int* in_sizes, int n_in,
                              void* d_out, int out_size)
{
    (void)in_sizes; (void)n_in; (void)out_size;
    const float* x  = (const float*)d_in[0];
    const float* W0 = (const float*)d_in[1];
    const float* b0 = (const float*)d_in[2];
    const float* Wf = (const float*)d_in[3];
    const float* bf = (const float*)d_in[4];
    const float* Wb = (const float*)d_in[5];
    const float* bb = (const float*)d_in[6];
    const float* W1 = (const float*)d_in[7];
    const float* b1 = (const float*)d_in[8];
    const float* W2 = (const float*)d_in[9];
    const float* b2 = (const float*)d_in[10];
    const float* W3 = (const float*)d_in[11];
    const float* b3 = (const float*)d_in[12];
    float* out = (float*)d_out;

    const int smem1 = (T_ * XPAD + D_ * E_ + 64 + E_ * G4_ + 64 + E_ * T_) * (int)sizeof(float);
    cudaFuncSetAttribute(k_phase1, cudaFuncAttributeMaxDynamicSharedMemorySize, smem1);

    k_phase1<<<B_,     256, smem1>>>(x, W0, b0, Wf, bf);
    k_scan  <<<B_ / 4, 128>>>(Wf);
    k_tail  <<<B_ / 8, 256>>>(x, W0, b0, Wb, bb, W1, b1, W2, b2, W3, b3, out);
}

// round 5
// speedup vs baseline: 1.3636x; 1.2554x over previous
#include <cuda_runtime.h>
#include <cuda_bf16.h>
#include <cstdint>

#define B_  4096
#define T_  256
#define D_  20
#define E_  64
#define H_  16
#define G4_ 64
#define TGRP 32
#define SGROW 80

// G layout: [b][t(256)][c(64)] contiguous per b
__device__ float g_G[(size_t)B_ * G4_ * T_];
__device__ float g_hf[B_ * H_];

typedef unsigned long long u64;

__device__ __forceinline__ float ex2a(float x){ float y; asm("ex2.approx.f32 %0,%1;":"=f"(y):"f"(x)); return y; }
__device__ __forceinline__ float rcpa(float x){ float y; asm("rcp.approx.f32 %0,%1;":"=f"(y):"f"(x)); return y; }
__device__ __forceinline__ u64 pack2(float a,float b){ u64 r; asm("mov.b64 %0,{%1,%2};":"=l"(r):"f"(a),"f"(b)); return r; }
__device__ __forceinline__ void unpack2(u64 v,float&a,float&b){ asm("mov.b64 {%0,%1},%2;":"=f"(a),"=f"(b):"l"(v)); }
__device__ __forceinline__ u64 fma2(u64 a,u64 b,u64 c){ u64 d; asm("fma.rn.f32x2 %0,%1,%2,%3;":"=l"(d):"l"(a),"l"(b),"l"(c)); return d; }
__device__ __forceinline__ u64 add2(u64 a,u64 b){ u64 d; asm("add.rn.f32x2 %0,%1,%2;":"=l"(d):"l"(a),"l"(b)); return d; }
__device__ __forceinline__ uint32_t smem_u32(const void* p){
    uint32_t a; asm("{ .reg .u64 t; cvta.to.shared.u64 t, %1; cvt.u32.u64 %0, t; }":"=r"(a):"l"(p)); return a;
}
__device__ __forceinline__ void mma16816(float& c0, float& c1, float& c2, float& c3,
                                         uint32_t a0, uint32_t a1, uint32_t a2, uint32_t a3,
                                         uint32_t b0, uint32_t b1){
    asm volatile("mma.sync.aligned.m16n8k16.row.col.f32.bf16.bf16.f32 "
        "{%0,%1,%2,%3}, {%4,%5,%6,%7}, {%8,%9}, {%0,%1,%2,%3};"
        : "+f"(c0),"+f"(c1),"+f"(c2),"+f"(c3)
        : "r"(a0),"r"(a1),"r"(a2),"r"(a3),"r"(b0),"r"(b1));
}
__device__ __forceinline__ void ldm4(uint32_t& r0, uint32_t& r1, uint32_t& r2, uint32_t& r3, uint32_t a){
    asm volatile("ldmatrix.sync.aligned.m8n8.x4.shared.b16 {%0,%1,%2,%3}, [%4];"
        : "=r"(r0),"=r"(r1),"=r"(r2),"=r"(r3) : "r"(a));
}
// relu + bf16 hi/lo split of a packed f32 pair
__device__ __forceinline__ void split2(u64 p, uint32_t& hi, uint32_t& lo){
    float v0, v1; unpack2(p, v0, v1);
    v0 = fmaxf(v0, 0.f); v1 = fmaxf(v1, 0.f);
    __nv_bfloat16 h0 = __float2bfloat16(v0), h1 = __float2bfloat16(v1);
    __nv_bfloat16 l0 = __float2bfloat16(v0 - __bfloat162float(h0));
    __nv_bfloat16 l1 = __float2bfloat16(v1 - __bfloat162float(h1));
    hi = (uint32_t)__bfloat16_as_ushort(h0) | ((uint32_t)__bfloat16_as_ushort(h1) << 16);
    lo = (uint32_t)__bfloat16_as_ushort(l0) | ((uint32_t)__bfloat16_as_ushort(l1) << 16);
}

// SMEM byte offsets (phase1)
#define OAH 0u          // hE hi tiles: 256 rows x 144B
#define OAL 36864u      // hE lo tiles
#define OWH 73728u      // WfT hi: 64 rows x 144B
#define OWL 82944u
#define OW0 92160u      // W0: 20x64 f32
#define OB0 97280u
#define OBF 97536u
#define SMEM1 97792u

// ---------------- Phase 1: FFMA step A + HMMA (bf16 3-split) step B ----------------
__global__ void __launch_bounds__(256, 2) k_phase1(
    const float* __restrict__ x, const float* __restrict__ W0,
    const float* __restrict__ b0, const float* __restrict__ Wf,
    const float* __restrict__ bf)
{
    extern __shared__ char sm[];
    const uint32_t sb = smem_u32(sm);
    float* W0s = (float*)(sm + OW0);
    float* b0s = (float*)(sm + OB0);
    float* bfs = (float*)(sm + OBF);

    const int tid = threadIdx.x, wid = tid >> 5, lane = tid & 31;
    const int b = blockIdx.x;

    // weights / biases to smem; WfT hi/lo split, [c][k] rows of 144B
    for (int i = tid; i < D_ * E_; i += 256) W0s[i] = W0[i];
    if (tid < 64) { b0s[tid] = b0[tid]; bfs[tid] = bf[tid]; }
    for (int i = tid; i < 4096; i += 256) {
        int k = i >> 6, c = i & 63;
        float v = Wf[i];
        __nv_bfloat16 h = __float2bfloat16(v);
        __nv_bfloat16 l = __float2bfloat16(v - __bfloat162float(h));
        *(unsigned short*)(sm + OWH + c * 144 + k * 2) = __bfloat16_as_ushort(h);
        *(unsigned short*)(sm + OWL + c * 144 + k * 2) = __bfloat16_as_ushort(l);
    }
    __syncthreads();

    // ---- Step A: thread t computes hE[t][0..63], writes bf16 hi/lo tiles ----
    {
        const int t = tid;
        const float4* xp4 = (const float4*)(x + (size_t)b * (T_ * D_) + t * D_);
        float xv[20];
        #pragma unroll
        for (int q = 0; q < 5; q++) {
            float4 f = __ldg(xp4 + q);
            xv[4*q] = f.x; xv[4*q+1] = f.y; xv[4*q+2] = f.z; xv[4*q+3] = f.w;
        }
        u64 acc2[32];
        #pragma unroll
        for (int q = 0; q < 32; q++) acc2[q] = pack2(b0s[2*q], b0s[2*q+1]);
        #pragma unroll 4
        for (int d = 0; d < D_; d++) {
            u64 xp = pack2(xv[d], xv[d]);
            const ulonglong2* wr = (const ulonglong2*)&W0s[d * 64];
            #pragma unroll
            for (int q = 0; q < 16; q++) {
                ulonglong2 ww = wr[q];
                acc2[2*q]   = fma2(xp, ww.x, acc2[2*q]);
                acc2[2*q+1] = fma2(xp, ww.y, acc2[2*q+1]);
            }
        }
        #pragma unroll
        for (int q4 = 0; q4 < 8; q4++) {
            uint4 hv, lv;
            split2(acc2[4*q4+0], hv.x, lv.x);
            split2(acc2[4*q4+1], hv.y, lv.y);
            split2(acc2[4*q4+2], hv.z, lv.z);
            split2(acc2[4*q4+3], hv.w, lv.w);
            *(uint4*)(sm + OAH + t * 144 + q4 * 16) = hv;
            *(uint4*)(sm + OAL + t * 144 + q4 * 16) = lv;
        }
    }
    __syncthreads();

    // ---- Step B: warp tile 32t x 64c, K=64, 3-term bf16 split HMMA ----
    float acc[2][8][4];
    #pragma unroll
    for (int m = 0; m < 2; m++)
        #pragma unroll
        for (int n = 0; n < 8; n++)
            #pragma unroll
            for (int i = 0; i < 4; i++) acc[m][n][i] = 0.f;

    const int t0 = wid * 32;
    const int arow = ((lane >> 3) & 1) * 8 + (lane & 7);
    const int acol = (lane >> 4) * 16;

    #pragma unroll
    for (int ks = 0; ks < 4; ks++) {
        const int k0 = ks * 16;
        uint32_t Ah[2][4], Al[2][4];
        #pragma unroll
        for (int mt = 0; mt < 2; mt++) {
            uint32_t ad = sb + OAH + (uint32_t)(t0 + mt * 16 + arow) * 144 + (uint32_t)(k0 * 2 + acol);
            ldm4(Ah[mt][0], Ah[mt][1], Ah[mt][2], Ah[mt][3], ad);
            ldm4(Al[mt][0], Al[mt][1], Al[mt][2], Al[mt][3], ad + (OAL - OAH));
        }
        #pragma unroll
        for (int nt = 0; nt < 8; nt++) {
            const uint32_t boff = (uint32_t)((nt * 8 + (lane >> 2)) * 144 + k0 * 2 + (lane & 3) * 4);
            uint32_t bh0 = *(const uint32_t*)(sm + OWH + boff);
            uint32_t bh1 = *(const uint32_t*)(sm + OWH + boff + 16);
            uint32_t bl0 = *(const uint32_t*)(sm + OWL + boff);
            uint32_t bl1 = *(const uint32_t*)(sm + OWL + boff + 16);
            #pragma unroll
            for (int mt = 0; mt < 2; mt++) {
                mma16816(acc[mt][nt][0], acc[mt][nt][1], acc[mt][nt][2], acc[mt][nt][3],
                         Ah[mt][0], Ah[mt][1], Ah[mt][2], Ah[mt][3], bh0, bh1);
                mma16816(acc[mt][nt][0], acc[mt][nt][1], acc[mt][nt][2], acc[mt][nt][3],
                         Ah[mt][0], Ah[mt][1], Ah[mt][2], Ah[mt][3], bl0, bl1);
                mma16816(acc[mt][nt][0], acc[mt][nt][1], acc[mt][nt][2], acc[mt][nt][3],
                         Al[mt][0], Al[mt][1], Al[mt][2], Al[mt][3], bh0, bh1);
            }
        }
    }
    __syncthreads();   // all A/W reads done; stage may overwrite

    // ---- Epilogue: +bias -> stage (72-float rows) -> coalesced STG ----
    {
        float* stage = (float*)sm;
        #pragma unroll
        for (int mt = 0; mt < 2; mt++) {
            const int t = t0 + mt * 16 + (lane >> 2);
            #pragma unroll
            for (int nt = 0; nt < 8; nt++) {
                const int c = nt * 8 + (lane & 3) * 2;
                float2 s0 = make_float2(acc[mt][nt][0] + bfs[c], acc[mt][nt][1] + bfs[c+1]);
                float2 s1 = make_float2(acc[mt][nt][2] + bfs[c], acc[mt][nt][3] + bfs[c+1]);
                *(float2*)&stage[(size_t)t * 72 + c]       = s0;
                *(float2*)&stage[(size_t)(t + 8) * 72 + c] = s1;
            }
        }
        __syncthreads();
        float4* Gb4 = (float4*)(g_G + (size_t)b * (G4_ * T_));
        for (int i = tid; i < 4096; i += 256) {
            int t = i >> 4, c4 = i & 15;
            Gb4[i] = *(float4*)&stage[(size_t)t * 72 + c4 * 4];
        }
    }
}

// ---------------- Phase 2: forward scan (unchanged, known-good) ----------------
__global__ void __launch_bounds__(128) k_scan(const float* __restrict__ Wf)
{
    __shared__ float sg[4][2][8 * SGROW];
    __shared__ __align__(16) float2 hsh[4][16];

    const int tid = threadIdx.x, w = tid >> 5, l = tid & 31;
    const int b = blockIdx.x * 4 + w;
    const int j = l & 15;
    const int cA = (l < 16) ? l : (32 + j);
    const int cB = cA + 16;
    const int offA = cA + ((cA >> 5) << 4);
    const int offB = cB + ((cB >> 5) << 4);

    u64 wp[16];
    #pragma unroll
    for (int k = 0; k < 16; k++)
        wp[k] = pack2(Wf[(E_ + k) * G4_ + cA], Wf[(E_ + k) * G4_ + cB]);

    const float* Gb = g_G + (size_t)b * (G4_ * T_);

    int soff[4];
    #pragma unroll
    for (int k = 0; k < 4; k++) {
        int f  = l + 32 * k;
        int ti = f >> 4;
        int c4 = f & 15;
        soff[k] = ti * SGROW + c4 * 4 + ((c4 >> 3) << 4);
    }

    float h = 0.f, c = 0.f;
    if (l < 16) hsh[w][l] = make_float2(0.f, 0.f);

    const float L2E = 1.4426950408889634f;
    float kU, bU, kV, aV, bV;
    if (l < 16) { kU = -L2E; bU = 0.f;   kV = -2.f * L2E; aV = 2.f; bV = -1.f; }
    else        { kU = -L2E; bU = -L2E;  kV = -L2E;       aV = 1.f; bV =  0.f; }

    float4 r[4];
    {
        const float4* src = (const float4*)Gb;
        #pragma unroll
        for (int k = 0; k < 4; k++) r[k] = src[l + 32 * k];
        #pragma unroll
        for (int k = 0; k < 4; k++) *(float4*)&sg[w][0][soff[k]] = r[k];
    }
    __syncwarp();

    for (int tg = 0; tg < TGRP; ++tg) {
        const int buf = tg & 1;
        if (tg < TGRP - 1) {
            const float4* src = (const float4*)(Gb + (size_t)(tg + 1) * 512);
            #pragma unroll
            for (int k = 0; k < 4; k++) r[k] = src[l + 32 * k];
        }
        const float* sgb = &sg[w][buf][0];
        #pragma unroll
        for (int i = 0; i < 8; i++) {
            float ga = sgb[i * SGROW + offA];
            float gb = sgb[i * SGROW + offB];
            const ulonglong2* hp = (const ulonglong2*)&hsh[w][0];
            ulonglong2 h01 = hp[0], h23 = hp[1], h45 = hp[2], h67 = hp[3];
            ulonglong2 h89 = hp[4], hab = hp[5], hcd = hp[6], hef = hp[7];
            u64 a0p = pack2(ga, gb);
            a0p = fma2(h01.x, wp[0],  a0p); a0p = fma2(h01.y, wp[1],  a0p);
            a0p = fma2(h23.x, wp[2],  a0p); a0p = fma2(h23.y, wp[3],  a0p);
            u64 a1p = fma2(h45.x, wp[4], 0ULL); a1p = fma2(h45.y, wp[5],  a1p);
            a1p = fma2(h67.x, wp[6],  a1p); a1p = fma2(h67.y, wp[7],  a1p);
            u64 a2p = fma2(h89.x, wp[8], 0ULL); a2p = fma2(h89.y, wp[9],  a2p);
            a2p = fma2(hab.x, wp[10], a2p); a2p = fma2(hab.y, wp[11], a2p);
            u64 a3p = fma2(hcd.x, wp[12], 0ULL); a3p = fma2(hcd.y, wp[13], a3p);
            a3p = fma2(hef.x, wp[14], a3p); a3p = fma2(hef.y, wp[15], a3p);
            u64 acc = add2(add2(a0p, a1p), add2(a2p, a3p));
            float xA, xB; unpack2(acc, xA, xB);

            float u = rcpa(1.f + ex2a(fmaf(kU, xA, bU)));
            float v = fmaf(aV, rcpa(1.f + ex2a(kV * xB)), bV);
            float sf = __shfl_down_sync(0xffffffffu, u, 16);
            float so = __shfl_down_sync(0xffffffffu, v, 16);
            if (l < 16) {
                c = fmaf(sf, c, u * v);
                float th = fmaf(2.f, rcpa(1.f + ex2a(-2.f * L2E * c)), -1.f);
                h = so * th;
                hsh[w][l] = make_float2(h, h);
            }
            __syncwarp();
        }
        if (tg < TGRP - 1) {
            #pragma unroll
            for (int k = 0; k < 4; k++) *(float4*)&sg[w][buf ^ 1][soff[k]] = r[k];
            __syncwarp();
        }
    }
    if (l < 16) g_hf[b * H_ + l] = h;
}

// ---------------- Tail: bwd single step + head MLP (unchanged) ----------------
__global__ void __launch_bounds__(256) k_tail(
    const float* __restrict__ x, const float* __restrict__ W0,
    const float* __restrict__ b0, const float* __restrict__ Wb,
    const float* __restrict__ bb,
    const float* __restrict__ W1, const float* __restrict__ b1,
    const float* __restrict__ W2, const float* __restrict__ b2,
    const float* __restrict__ W3, const float* __restrict__ b3,
    float* __restrict__ out)
{
    __shared__ float W0s[D_ * E_];
    __shared__ float Wbs[E_ * G4_];
    __shared__ float b0s[64], bbs[64];
    __shared__ float W1s[32 * 64], W2s[64 * 16], W3s[32];
    __shared__ float b1s[64], b2s[16], b3s[2];
    __shared__ float xsh[8][20];
    __shared__ __align__(16) float2 hes[8][64];
    __shared__ float hbs[8][16];
    __shared__ float insh[8][32], ush[8][64], vsh[8][16];

    const int tid = threadIdx.x, w = tid >> 5, l = tid & 31;
    const int b = blockIdx.x * 8 + w;

    for (int i = tid; i < D_ * E_;  i += 256) W0s[i] = W0[i];
    for (int i = tid; i < E_ * G4_; i += 256) Wbs[i] = Wb[i];
    for (int i = tid; i < 32 * 64;  i += 256) W1s[i] = W1[i];
    for (int i = tid; i < 64 * 16;  i += 256) W2s[i] = W2[i];
    if (tid < 32) W3s[tid] = W3[tid];
    if (tid < 64) { b0s[tid] = b0[tid]; bbs[tid] = bb[tid]; b1s[tid] = b1[tid]; }
    if (tid < 16) b2s[tid] = b2[tid];
    if (tid < 2)  b3s[tid] = b3[tid];
    __syncthreads();

    if (l < 20) xsh[w][l] = x[((size_t)b * T_ + (T_ - 1)) * D_ + l];
    __syncwarp();

    float a0 = b0s[l], a1 = b0s[l + 32];
    #pragma unroll
    for (int d = 0; d < D_; d++) {
        float xv = xsh[w][d];
        a0 = fmaf(xv, W0s[d * E_ + l],      a0);
        a1 = fmaf(xv, W0s[d * E_ + l + 32], a1);
    }
    a0 = fmaxf(a0, 0.f); a1 = fmaxf(a1, 0.f);
    hes[w][l]      = make_float2(a0, a0);
    hes[w][l + 32] = make_float2(a1, a1);
    __syncwarp();

    const int j = l & 15;
    const int cA = (l < 16) ? l : (32 + j);
    const int cB = cA + 16;
    u64 acc = pack2(bbs[cA], bbs[cB]);
    #pragma unroll 8
    for (int k = 0; k < E_; k++) {
        u64 hd = *(const u64*)&hes[w][k];
        acc = fma2(hd, pack2(Wbs[k * G4_ + cA], Wbs[k * G4_ + cB]), acc);
    }
    float xA, xB; unpack2(acc, xA, xB);

    const float L2E = 1.4426950408889634f;
    float kU, bU, kV, aV, bV;
    if (l < 16) { kU = -L2E; bU = 0.f;  kV = -2.f * L2E; aV = 2.f; bV = -1.f; }
    else        { kU = -L2E; bU = -L2E; kV = -L2E;       aV = 1.f; bV =  0.f; }
    float u = rcpa(1.f + ex2a(fmaf(kU, xA, bU)));
    float v = fmaf(aV, rcpa(1.f + ex2a(kV * xB)), bV);
    float so = __shfl_down_sync(0xffffffffu, v, 16);
    if (l < 16) {
        float cc = u * v;
        float th = fmaf(2.f, rcpa(1.f + ex2a(-2.f * L2E * cc)), -1.f);
        hbs[w][l] = so * th;
    }
    __syncwarp();

    insh[w][l] = (l < 16) ? g_hf[b * H_ + l] : hbs[w][l - 16];
    __syncwarp();

    float u0 = b1s[l], u1 = b1s[l + 32];
    #pragma unroll 8
    for (int k = 0; k < 32; k++) {
        float t = insh[w][k];
        u0 = fmaf(t, W1s[k * 64 + l],      u0);
        u1 = fmaf(t, W1s[k * 64 + l + 32], u1);
    }
    ush[w][l]      = fmaxf(u0, 0.f);
    ush[w][l + 32] = fmaxf(u1, 0.f);
    __syncwarp();

    if (l < 16) {
        float a = b2s[l];
        #pragma unroll 8
        for (int k = 0; k < 64; k++) a = fmaf(ush[w][k], W2s[k * 16 + l], a);
        vsh[w][l] = fmaxf(a, 0.f);
    }
    __syncwarp();

    if (l < 2) {
        float a = b3s[l];
        #pragma unroll
        for (int k = 0; k < 16; k++) a = fmaf(vsh[w][k], W3s[k * 2 + l], a);
        out[b * 2 + l] = a;
    }
}

extern "C" void kernel_launch(void* const* d_in, const int* in_sizes, int n_in,
                              void* d_out, int out_size)
{
    (void)in_sizes; (void)n_in; (void)out_size;
    const float* x  = (const float*)d_in[0];
    const float* W0 = (const float*)d_in[1];
    const float* b0 = (const float*)d_in[2];
    const float* Wf = (const float*)d_in[3];
    const float* bf = (const float*)d_in[4];
    const float* Wb = (const float*)d_in[5];
    const float* bb = (const float*)d_in[6];
    const float* W1 = (const float*)d_in[7];
    const float* b1 = (const float*)d_in[8];
    const float* W2 = (const float*)d_in[9];
    const float* b2 = (const float*)d_in[10];
    const float* W3 = (const float*)d_in[11];
    const float* b3 = (const float*)d_in[12];
    float* out = (float*)d_out;

    cudaFuncSetAttribute(k_phase1, cudaFuncAttributeMaxDynamicSharedMemorySize, (int)SMEM1);

    k_phase1<<<B_,     256, SMEM1>>>(x, W0, b0, Wf, bf);
    k_scan  <<<B_ / 4, 128>>>(Wf);
    k_tail  <<<B_ / 8, 256>>>(x, W0, b0, Wb, bb, W1, b1, W2, b2, W3, b3, out);
}

// round 6
// speedup vs baseline: 1.4042x; 1.0297x over previous
#include <cuda_runtime.h>
#include <cuda_bf16.h>
#include <cstdint>

#define B_  4096
#define T_  256
#define D_  20
#define E_  64
#define H_  16
#define G4_ 64
#define TGRP 32
#define SGROW 80

// G layout: [b][t(256)][c(64)]
__device__ float g_G[(size_t)B_ * G4_ * T_];
__device__ float g_hf[B_ * H_];

typedef unsigned long long u64;

__device__ __forceinline__ float ex2a(float x){ float y; asm("ex2.approx.f32 %0,%1;":"=f"(y):"f"(x)); return y; }
__device__ __forceinline__ float rcpa(float x){ float y; asm("rcp.approx.f32 %0,%1;":"=f"(y):"f"(x)); return y; }
__device__ __forceinline__ u64 pack2(float a,float b){ u64 r; asm("mov.b64 %0,{%1,%2};":"=l"(r):"f"(a),"f"(b)); return r; }
__device__ __forceinline__ void unpack2(u64 v,float&a,float&b){ asm("mov.b64 {%0,%1},%2;":"=f"(a),"=f"(b):"l"(v)); }
__device__ __forceinline__ u64 fma2(u64 a,u64 b,u64 c){ u64 d; asm("fma.rn.f32x2 %0,%1,%2,%3;":"=l"(d):"l"(a),"l"(b),"l"(c)); return d; }
__device__ __forceinline__ u64 add2(u64 a,u64 b){ u64 d; asm("add.rn.f32x2 %0,%1,%2;":"=l"(d):"l"(a),"l"(b)); return d; }
__device__ __forceinline__ uint32_t smem_u32(const void* p){
    uint32_t a; asm("{ .reg .u64 t; cvta.to.shared.u64 t, %1; cvt.u32.u64 %0, t; }":"=r"(a):"l"(p)); return a;
}
__device__ __forceinline__ void mma16816(float& c0, float& c1, float& c2, float& c3,
                                         uint32_t a0, uint32_t a1, uint32_t a2, uint32_t a3,
                                         uint32_t b0, uint32_t b1){
    asm volatile("mma.sync.aligned.m16n8k16.row.col.f32.bf16.bf16.f32 "
        "{%0,%1,%2,%3}, {%4,%5,%6,%7}, {%8,%9}, {%0,%1,%2,%3};"
        : "+f"(c0),"+f"(c1),"+f"(c2),"+f"(c3)
        : "r"(a0),"r"(a1),"r"(a2),"r"(a3),"r"(b0),"r"(b1));
}
__device__ __forceinline__ void ldm4(uint32_t& r0, uint32_t& r1, uint32_t& r2, uint32_t& r3, uint32_t a){
    asm volatile("ldmatrix.sync.aligned.m8n8.x4.shared.b16 {%0,%1,%2,%3}, [%4];"
        : "=r"(r0),"=r"(r1),"=r"(r2),"=r"(r3) : "r"(a));
}
__device__ __forceinline__ void split2(u64 p, uint32_t& hi, uint32_t& lo){
    float v0, v1; unpack2(p, v0, v1);
    v0 = fmaxf(v0, 0.f); v1 = fmaxf(v1, 0.f);
    __nv_bfloat16 h0 = __float2bfloat16(v0), h1 = __float2bfloat16(v1);
    __nv_bfloat16 l0 = __float2bfloat16(v0 - __bfloat162float(h0));
    __nv_bfloat16 l1 = __float2bfloat16(v1 - __bfloat162float(h1));
    hi = (uint32_t)__bfloat16_as_ushort(h0) | ((uint32_t)__bfloat16_as_ushort(h1) << 16);
    lo = (uint32_t)__bfloat16_as_ushort(l0) | ((uint32_t)__bfloat16_as_ushort(l1) << 16);
}

// SMEM byte offsets (phase1)
#define OAH 0u
#define OAL 36864u
#define OWH 73728u
#define OWL 82944u
#define OW0 92160u
#define OB0 97280u
#define OBF 97536u
#define SMEM1 97792u

// ---------------- Phase 1: FFMA step A + HMMA (bf16 3-split), direct STG ----------------
__global__ void __launch_bounds__(256, 2) k_phase1(
    const float* __restrict__ x, const float* __restrict__ W0,
    const float* __restrict__ b0, const float* __restrict__ Wf,
    const float* __restrict__ bf)
{
    extern __shared__ char sm[];
    const uint32_t sb = smem_u32(sm);
    float* W0s = (float*)(sm + OW0);
    float* b0s = (float*)(sm + OB0);
    float* bfs = (float*)(sm + OBF);

    const int tid = threadIdx.x, wid = tid >> 5, lane = tid & 31;
    const int b = blockIdx.x;

    for (int i = tid; i < D_ * E_; i += 256) W0s[i] = W0[i];
    if (tid < 64) { b0s[tid] = b0[tid]; bfs[tid] = bf[tid]; }
    for (int i = tid; i < 4096; i += 256) {
        int k = i >> 6, c = i & 63;
        float v = Wf[i];
        __nv_bfloat16 h = __float2bfloat16(v);
        __nv_bfloat16 l = __float2bfloat16(v - __bfloat162float(h));
        *(unsigned short*)(sm + OWH + c * 144 + k * 2) = __bfloat16_as_ushort(h);
        *(unsigned short*)(sm + OWL + c * 144 + k * 2) = __bfloat16_as_ushort(l);
    }
    __syncthreads();

    // ---- Step A ----
    {
        const int t = tid;
        const float4* xp4 = (const float4*)(x + (size_t)b * (T_ * D_) + t * D_);
        float xv[20];
        #pragma unroll
        for (int q = 0; q < 5; q++) {
            float4 f = __ldg(xp4 + q);
            xv[4*q] = f.x; xv[4*q+1] = f.y; xv[4*q+2] = f.z; xv[4*q+3] = f.w;
        }
        u64 acc2[32];
        #pragma unroll
        for (int q = 0; q < 32; q++) acc2[q] = pack2(b0s[2*q], b0s[2*q+1]);
        #pragma unroll 4
        for (int d = 0; d < D_; d++) {
            u64 xp = pack2(xv[d], xv[d]);
            const ulonglong2* wr = (const ulonglong2*)&W0s[d * 64];
            #pragma unroll
            for (int q = 0; q < 16; q++) {
                ulonglong2 ww = wr[q];
                acc2[2*q]   = fma2(xp, ww.x, acc2[2*q]);
                acc2[2*q+1] = fma2(xp, ww.y, acc2[2*q+1]);
            }
        }
        #pragma unroll
        for (int q4 = 0; q4 < 8; q4++) {
            uint4 hv, lv;
            split2(acc2[4*q4+0], hv.x, lv.x);
            split2(acc2[4*q4+1], hv.y, lv.y);
            split2(acc2[4*q4+2], hv.z, lv.z);
            split2(acc2[4*q4+3], hv.w, lv.w);
            *(uint4*)(sm + OAH + t * 144 + q4 * 16) = hv;
            *(uint4*)(sm + OAL + t * 144 + q4 * 16) = lv;
        }
    }
    __syncthreads();

    // ---- Step B: bias-initialized accumulators, 3-term split HMMA ----
    float acc[2][8][4];
    {
        const int cb = (lane & 3) * 2;
        #pragma unroll
        for (int nt = 0; nt < 8; nt++) {
            float2 bv = *(float2*)&bfs[nt * 8 + cb];
            #pragma unroll
            for (int m = 0; m < 2; m++) {
                acc[m][nt][0] = bv.x; acc[m][nt][1] = bv.y;
                acc[m][nt][2] = bv.x; acc[m][nt][3] = bv.y;
            }
        }
    }

    const int t0 = wid * 32;
    const int arow = ((lane >> 3) & 1) * 8 + (lane & 7);
    const int acol = (lane >> 4) * 16;

    #pragma unroll
    for (int ks = 0; ks < 4; ks++) {
        const int k0 = ks * 16;
        uint32_t Ah[2][4], Al[2][4];
        #pragma unroll
        for (int mt = 0; mt < 2; mt++) {
            uint32_t ad = sb + OAH + (uint32_t)(t0 + mt * 16 + arow) * 144 + (uint32_t)(k0 * 2 + acol);
            ldm4(Ah[mt][0], Ah[mt][1], Ah[mt][2], Ah[mt][3], ad);
            ldm4(Al[mt][0], Al[mt][1], Al[mt][2], Al[mt][3], ad + (OAL - OAH));
        }
        #pragma unroll
        for (int nt = 0; nt < 8; nt++) {
            const uint32_t boff = (uint32_t)((nt * 8 + (lane >> 2)) * 144 + k0 * 2 + (lane & 3) * 4);
            uint32_t bh0 = *(const uint32_t*)(sm + OWH + boff);
            uint32_t bh1 = *(const uint32_t*)(sm + OWH + boff + 16);
            uint32_t bl0 = *(const uint32_t*)(sm + OWL + boff);
            uint32_t bl1 = *(const uint32_t*)(sm + OWL + boff + 16);
            #pragma unroll
            for (int mt = 0; mt < 2; mt++) {
                mma16816(acc[mt][nt][0], acc[mt][nt][1], acc[mt][nt][2], acc[mt][nt][3],
                         Ah[mt][0], Ah[mt][1], Ah[mt][2], Ah[mt][3], bh0, bh1);
                mma16816(acc[mt][nt][0], acc[mt][nt][1], acc[mt][nt][2], acc[mt][nt][3],
                         Ah[mt][0], Ah[mt][1], Ah[mt][2], Ah[mt][3], bl0, bl1);
                mma16816(acc[mt][nt][0], acc[mt][nt][1], acc[mt][nt][2], acc[mt][nt][3],
                         Al[mt][0], Al[mt][1], Al[mt][2], Al[mt][3], bh0, bh1);
            }
        }
    }

    // ---- Direct fragment stores (8 full 32B sectors per STG.64) ----
    {
        float* Gb = g_G + (size_t)b * (G4_ * T_);
        const int cb = (lane & 3) * 2;
        #pragma unroll
        for (int mt = 0; mt < 2; mt++) {
            const int t = t0 + mt * 16 + (lane >> 2);
            #pragma unroll
            for (int nt = 0; nt < 8; nt++) {
                const int c = nt * 8 + cb;
                *(float2*)&Gb[(size_t)t * 64 + c]       = make_float2(acc[mt][nt][0], acc[mt][nt][1]);
                *(float2*)&Gb[(size_t)(t + 8) * 64 + c] = make_float2(acc[mt][nt][2], acc[mt][nt][3]);
            }
        }
    }
}

// ---------------- Phase 2: forward scan, shfl-based h broadcast ----------------
__global__ void __launch_bounds__(128) k_scan(const float* __restrict__ Wf)
{
    __shared__ float sg[4][2][8 * SGROW];

    const int tid = threadIdx.x, w = tid >> 5, l = tid & 31;
    const int b = blockIdx.x * 4 + w;
    const int j = l & 15;
    const int cA = (l < 16) ? l : (32 + j);
    const int cB = cA + 16;
    const int offA = cA + ((cA >> 5) << 4);
    const int offB = cB + ((cB >> 5) << 4);

    u64 wp[16];
    #pragma unroll
    for (int k = 0; k < 16; k++)
        wp[k] = pack2(Wf[(E_ + k) * G4_ + cA], Wf[(E_ + k) * G4_ + cB]);

    const float* Gb = g_G + (size_t)b * (G4_ * T_);

    int soff[4];
    #pragma unroll
    for (int k = 0; k < 4; k++) {
        int f  = l + 32 * k;
        int ti = f >> 4;
        int c4 = f & 15;
        soff[k] = ti * SGROW + c4 * 4 + ((c4 >> 3) << 4);
    }

    float h = 0.f, c = 0.f;

    const float L2E = 1.4426950408889634f;
    float kU, bU, kV, aV, bV;
    if (l < 16) { kU = -L2E; bU = 0.f;   kV = -2.f * L2E; aV = 2.f; bV = -1.f; }
    else        { kU = -L2E; bU = -L2E;  kV = -L2E;       aV = 1.f; bV =  0.f; }

    float4 r[4];
    {
        const float4* src = (const float4*)Gb;
        #pragma unroll
        for (int k = 0; k < 4; k++) r[k] = src[l + 32 * k];
        #pragma unroll
        for (int k = 0; k < 4; k++) *(float4*)&sg[w][0][soff[k]] = r[k];
    }
    __syncwarp();

    for (int tg = 0; tg < TGRP; ++tg) {
        const int buf = tg & 1;
        if (tg < TGRP - 1) {
            const float4* src = (const float4*)(Gb + (size_t)(tg + 1) * 512);
            #pragma unroll
            for (int k = 0; k < 4; k++) r[k] = src[l + 32 * k];
        }
        const float* sgb = &sg[w][buf][0];
        #pragma unroll
        for (int i = 0; i < 8; i++) {
            float ga = sgb[i * SGROW + offA];
            float gb = sgb[i * SGROW + offB];
            // broadcast h[0..15] from lanes 0-15
            float h0  = __shfl_sync(0xffffffffu, h, 0);
            float h1  = __shfl_sync(0xffffffffu, h, 1);
            float h2  = __shfl_sync(0xffffffffu, h, 2);
            float h3  = __shfl_sync(0xffffffffu, h, 3);
            float h4  = __shfl_sync(0xffffffffu, h, 4);
            float h5  = __shfl_sync(0xffffffffu, h, 5);
            float h6  = __shfl_sync(0xffffffffu, h, 6);
            float h7  = __shfl_sync(0xffffffffu, h, 7);
            float h8  = __shfl_sync(0xffffffffu, h, 8);
            float h9  = __shfl_sync(0xffffffffu, h, 9);
            float h10 = __shfl_sync(0xffffffffu, h, 10);
            float h11 = __shfl_sync(0xffffffffu, h, 11);
            float h12 = __shfl_sync(0xffffffffu, h, 12);
            float h13 = __shfl_sync(0xffffffffu, h, 13);
            float h14 = __shfl_sync(0xffffffffu, h, 14);
            float h15 = __shfl_sync(0xffffffffu, h, 15);

            u64 a0p = pack2(ga, gb);
            a0p = fma2(pack2(h0, h0),   wp[0],  a0p);
            a0p = fma2(pack2(h1, h1),   wp[1],  a0p);
            a0p = fma2(pack2(h2, h2),   wp[2],  a0p);
            a0p = fma2(pack2(h3, h3),   wp[3],  a0p);
            u64 a1p = fma2(pack2(h4, h4),   wp[4],  0ULL);
            a1p = fma2(pack2(h5, h5),   wp[5],  a1p);
            a1p = fma2(pack2(h6, h6),   wp[6],  a1p);
            a1p = fma2(pack2(h7, h7),   wp[7],  a1p);
            u64 a2p = fma2(pack2(h8, h8),   wp[8],  0ULL);
            a2p = fma2(pack2(h9, h9),   wp[9],  a2p);
            a2p = fma2(pack2(h10, h10), wp[10], a2p);
            a2p = fma2(pack2(h11, h11), wp[11], a2p);
            u64 a3p = fma2(pack2(h12, h12), wp[12], 0ULL);
            a3p = fma2(pack2(h13, h13), wp[13], a3p);
            a3p = fma2(pack2(h14, h14), wp[14], a3p);
            a3p = fma2(pack2(h15, h15), wp[15], a3p);
            u64 acc = add2(add2(a0p, a1p), add2(a2p, a3p));
            float xA, xB; unpack2(acc, xA, xB);

            float u = rcpa(1.f + ex2a(fmaf(kU, xA, bU)));
            float v = fmaf(aV, rcpa(1.f + ex2a(kV * xB)), bV);
            float sf = __shfl_down_sync(0xffffffffu, u, 16);
            float so = __shfl_down_sync(0xffffffffu, v, 16);
            if (l < 16) {
                c = fmaf(sf, c, u * v);
                float th = fmaf(2.f, rcpa(1.f + ex2a(-2.f * L2E * c)), -1.f);
                h = so * th;
            }
        }
        if (tg < TGRP - 1) {
            #pragma unroll
            for (int k = 0; k < 4; k++) *(float4*)&sg[w][buf ^ 1][soff[k]] = r[k];
            __syncwarp();
        }
    }
    if (l < 16) g_hf[b * H_ + l] = h;
}

// ---------------- Tail: bwd single step + head MLP ----------------
__global__ void __launch_bounds__(256) k_tail(
    const float* __restrict__ x, const float* __restrict__ W0,
    const float* __restrict__ b0, const float* __restrict__ Wb,
    const float* __restrict__ bb,
    const float* __restrict__ W1, const float* __restrict__ b1,
    const float* __restrict__ W2, const float* __restrict__ b2,
    const float* __restrict__ W3, const float* __restrict__ b3,
    float* __restrict__ out)
{
    __shared__ float W0s[D_ * E_];
    __shared__ float Wbs[E_ * G4_];
    __shared__ float b0s[64], bbs[64];
    __shared__ float W1s[32 * 64], W2s[64 * 16], W3s[32];
    __shared__ float b1s[64], b2s[16], b3s[2];
    __shared__ float xsh[8][20];
    __shared__ __align__(16) float2 hes[8][64];
    __shared__ float hbs[8][16];
    __shared__ float insh[8][32], ush[8][64], vsh[8][16];

    const int tid = threadIdx.x, w = tid >> 5, l = tid & 31;
    const int b = blockIdx.x * 8 + w;

    for (int i = tid; i < D_ * E_;  i += 256) W0s[i] = W0[i];
    for (int i = tid; i < E_ * G4_; i += 256) Wbs[i] = Wb[i];
    for (int i = tid; i < 32 * 64;  i += 256) W1s[i] = W1[i];
    for (int i = tid; i < 64 * 16;  i += 256) W2s[i] = W2[i];
    if (tid < 32) W3s[tid] = W3[tid];
    if (tid < 64) { b0s[tid] = b0[tid]; bbs[tid] = bb[tid]; b1s[tid] = b1[tid]; }
    if (tid < 16) b2s[tid] = b2[tid];
    if (tid < 2)  b3s[tid] = b3[tid];
    __syncthreads();

    if (l < 20) xsh[w][l] = x[((size_t)b * T_ + (T_ - 1)) * D_ + l];
    __syncwarp();

    float a0 = b0s[l], a1 = b0s[l + 32];
    #pragma unroll
    for (int d = 0; d < D_; d++) {
        float xv = xsh[w][d];
        a0 = fmaf(xv, W0s[d * E_ + l],      a0);
        a1 = fmaf(xv, W0s[d * E_ + l + 32], a1);
    }
    a0 = fmaxf(a0, 0.f); a1 = fmaxf(a1, 0.f);
    hes[w][l]      = make_float2(a0, a0);
    hes[w][l + 32] = make_float2(a1, a1);
    __syncwarp();

    const int j = l & 15;
    const int cA = (l < 16) ? l : (32 + j);
    const int cB = cA + 16;
    u64 acc = pack2(bbs[cA], bbs[cB]);
    #pragma unroll 8
    for (int k = 0; k < E_; k++) {
        u64 hd = *(const u64*)&hes[w][k];
        acc = fma2(hd, pack2(Wbs[k * G4_ + cA], Wbs[k * G4_ + cB]), acc);
    }
    float xA, xB; unpack2(acc, xA, xB);

    const float L2E = 1.4426950408889634f;
    float kU, bU, kV, aV, bV;
    if (l < 16) { kU = -L2E; bU = 0.f;  kV = -2.f * L2E; aV = 2.f; bV = -1.f; }
    else        { kU = -L2E; bU = -L2E; kV = -L2E;       aV = 1.f; bV =  0.f; }
    float u = rcpa(1.f + ex2a(fmaf(kU, xA, bU)));
    float v = fmaf(aV, rcpa(1.f + ex2a(kV * xB)), bV);
    float so = __shfl_down_sync(0xffffffffu, v, 16);
    if (l < 16) {
        float cc = u * v;
        float th = fmaf(2.f, rcpa(1.f + ex2a(-2.f * L2E * cc)), -1.f);
        hbs[w][l] = so * th;
    }
    __syncwarp();

    insh[w][l] = (l < 16) ? g_hf[b * H_ + l] : hbs[w][l - 16];
    __syncwarp();

    float u0 = b1s[l], u1 = b1s[l + 32];
    #pragma unroll 8
    for (int k = 0; k < 32; k++) {
        float t = insh[w][k];
        u0 = fmaf(t, W1s[k * 64 + l],      u0);
        u1 = fmaf(t, W1s[k * 64 + l + 32], u1);
    }
    ush[w][l]      = fmaxf(u0, 0.f);
    ush[w][l + 32] = fmaxf(u1, 0.f);
    __syncwarp();

    if (l < 16) {
        float a = b2s[l];
        #pragma unroll 8
        for (int k = 0; k < 64; k++) a = fmaf(ush[w][k], W2s[k * 16 + l], a);
        vsh[w][l] = fmaxf(a, 0.f);
    }
    __syncwarp();

    if (l < 2) {
        float a = b3s[l];
        #pragma unroll
        for (int k = 0; k < 16; k++) a = fmaf(vsh[w][k], W3s[k * 2 + l], a);
        out[b * 2 + l] = a;
    }
}

extern "C" void kernel_launch(void* const* d_in, const int* in_sizes, int n_in,
                              void* d_out, int out_size)
{
    (void)in_sizes; (void)n_in; (void)out_size;
    const float* x  = (const float*)d_in[0];
    const float* W0 = (const float*)d_in[1];
    const float* b0 = (const float*)d_in[2];
    const float* Wf = (const float*)d_in[3];
    const float* bf = (const float*)d_in[4];
    const float* Wb = (const float*)d_in[5];
    const float* bb = (const float*)d_in[6];
    const float* W1 = (const float*)d_in[7];
    const float* b1 = (const float*)d_in[8];
    const float* W2 = (const float*)d_in[9];
    const float* b2 = (const float*)d_in[10];
    const float* W3 = (const float*)d_in[11];
    const float* b3 = (const float*)d_in[12];
    float* out = (float*)d_out;

    cudaFuncSetAttribute(k_phase1, cudaFuncAttributeMaxDynamicSharedMemorySize, (int)SMEM1);

    k_phase1<<<B_,     256, SMEM1>>>(x, W0, b0, Wf, bf);
    k_scan  <<<B_ / 4, 128>>>(Wf);
    k_tail  <<<B_ / 8, 256>>>(x, W0, b0, Wb, bb, W1, b1, W2, b2, W3, b3, out);
}